// round 8
// baseline (speedup 1.0000x reference)
#include <cuda_runtime.h>
#include <cuda_bf16.h>
#include <cstdint>

// ---------------------------------------------------------------------------
// Problem: B=32, NINP=128, NHID=256, W=512, K=2, NLAYERS=3
//
// Scratch:
//   g_xbuf[lv][b][c][p], p in [0,513): p=0 is left pad = hidden[lv][b][c][1],
//                        p=1+w is x_list[lv][b][c][w]. Row stride XW=520.
//   g_ig[b][w][o]: conv-bank gate pre-activations for the current layer.
//
// Output (float32): [0,65536) x[:,:,:,-2:] (4,32,256,2)
//                   [65536,114688) nc[:,:,:,-2:] (3,32,256,2)
//                   [114688,163744) attns (3,32,511)
// ---------------------------------------------------------------------------

#define XW 520
#define NC_OFF   65536
#define ATTN_OFF 114688
#define SCAN_SMEM (131072 + 4096)

__device__ float g_xbuf[4][32][256][XW];   // ~68 MB
__device__ float g_ig[32][512][1024];      // ~67 MB

__device__ __forceinline__ float sigm(float x) { return 1.0f / (1.0f + expf(-x)); }

__device__ __forceinline__ uint32_t smem_u32(const void* p) {
    return (uint32_t)__cvta_generic_to_shared(p);
}
__device__ __forceinline__ uint32_t mapa_rank(uint32_t a, uint32_t r) {
    uint32_t d;
    asm("mapa.shared::cluster.u32 %0, %1, %2;" : "=r"(d) : "r"(a), "r"(r));
    return d;
}
__device__ __forceinline__ float ld_cluster_f32(uint32_t a) {
    uint32_t u;
    asm volatile("ld.shared::cluster.b32 %0, [%1];" : "=r"(u) : "r"(a) : "memory");
    return __uint_as_float(u);
}
__device__ __forceinline__ void cluster_sync_() {
    asm volatile("barrier.cluster.arrive.aligned;" ::: "memory");
    asm volatile("barrier.cluster.wait.aligned;" ::: "memory");
}

// ------------------------- pad init ----------------------------------------
__global__ void init_pads_kernel(const float* __restrict__ hidden) {
    int idx = blockIdx.x * blockDim.x + threadIdx.x;   // 4*32*256 = 32768
    if (idx >= 4 * 32 * 256) return;
    int lv = idx >> 13;
    int b  = (idx >> 8) & 31;
    int c  = idx & 255;
    g_xbuf[lv][b][c][0] = hidden[((size_t)((lv * 32 + b) * 256 + c)) * 2 + 1];
}

// ------------------------- x0 tail copy to output --------------------------
__global__ void copy_x0_kernel(float* __restrict__ out) {
    int idx = blockIdx.x * blockDim.x + threadIdx.x;   // 32*256*2 = 16384
    if (idx >= 16384) return;
    int tt = idx & 1;
    int h  = (idx >> 1) & 255;
    int b  = idx >> 9;
    out[idx] = g_xbuf[0][b][h][511 + tt];
}

// ------------------------- embedding GEMM ----------------------------------
// g_xbuf[0][b][o][1+w] = emb_b[o] + sum_c emb_w[o][c] * input[b][c][w]
// grid (2,4,32), 256 threads, 128x128 tile, 8x8 micro
__global__ void __launch_bounds__(256, 2)
emb_gemm_kernel(const float* __restrict__ input,
                const float* __restrict__ emb_w,
                const float* __restrict__ emb_b) {
    __shared__ float As[16][132];
    __shared__ float Bs[16][136];
    const int o0 = blockIdx.x * 128, w0 = blockIdx.y * 128, b = blockIdx.z;
    const int tid = threadIdx.x, tx = tid & 15, ty = tid >> 4;

    float acc[8][8];   // [jw][io]
#pragma unroll
    for (int j = 0; j < 8; j++)
#pragma unroll
        for (int i = 0; i < 8; i++) acc[j][i] = 0.f;

    for (int k0 = 0; k0 < 128; k0 += 16) {
        __syncthreads();
        {   // A: 128 rows (o) x 16 cols (k)
            int cg = tid & 3;
            int row = tid >> 2;   // 0..63
#pragma unroll
            for (int p = 0; p < 2; p++) {
                int r_ = row + p * 64;
                float4 v = *(const float4*)(emb_w + (size_t)(o0 + r_) * 128 + k0 + cg * 4);
                As[cg * 4 + 0][r_] = v.x; As[cg * 4 + 1][r_] = v.y;
                As[cg * 4 + 2][r_] = v.z; As[cg * 4 + 3][r_] = v.w;
            }
        }
        {   // B: 16 rows (k) x 128 cols (w)
            for (int i = tid; i < 512; i += 256) {
                int r = i >> 5, q = i & 31;
                float4 v = *(const float4*)(input + (size_t)(b * 128 + k0 + r) * 512 + w0 + q * 4);
                Bs[r][q * 4 + 0] = v.x; Bs[r][q * 4 + 1] = v.y;
                Bs[r][q * 4 + 2] = v.z; Bs[r][q * 4 + 3] = v.w;
            }
        }
        __syncthreads();
#pragma unroll
        for (int k = 0; k < 16; k++) {
            float4 a0 = *(const float4*)&As[k][ty * 8];
            float4 a1 = *(const float4*)&As[k][ty * 8 + 4];
            float4 b0 = *(const float4*)&Bs[k][tx * 8];
            float4 b1 = *(const float4*)&Bs[k][tx * 8 + 4];
            float av[8] = {a0.x, a0.y, a0.z, a0.w, a1.x, a1.y, a1.z, a1.w};
            float bv[8] = {b0.x, b0.y, b0.z, b0.w, b1.x, b1.y, b1.z, b1.w};
#pragma unroll
            for (int j = 0; j < 8; j++)
#pragma unroll
                for (int i = 0; i < 8; i++) acc[j][i] = fmaf(av[i], bv[j], acc[j][i]);
        }
    }
#pragma unroll
    for (int i = 0; i < 8; i++) {
        int o = o0 + ty * 8 + i;
        float bias = emb_b[o];
        float* dst = &g_xbuf[0][b][o][1 + w0 + tx * 8];
#pragma unroll
        for (int j = 0; j < 8; j++) dst[j] = acc[j][i] + bias;
    }
}

// ------------------------- conv-bank GEMM ----------------------------------
// g_ig[b][w][o] = sum_{j<=l} ( conv_b[off+j][o]
//               + sum_{kk<512} conv_w[off+j][o][kk] * g_xbuf[j][b][kk>>1][w + (kk&1)] )
// grid (8,4,32), 256 threads
__global__ void __launch_bounds__(256, 2)
conv_gemm_kernel(int l, const float* __restrict__ conv_w, const float* __restrict__ conv_b) {
    __shared__ float As[16][132];
    __shared__ float Bs[16][136];
    const int o0 = blockIdx.x * 128, w0 = blockIdx.y * 128, b = blockIdx.z;
    const int off = (l * (l + 1)) >> 1;
    const int tid = threadIdx.x, tx = tid & 15, ty = tid >> 4;

    float acc[8][8];   // [jw][io]
#pragma unroll
    for (int j = 0; j < 8; j++)
#pragma unroll
        for (int i = 0; i < 8; i++) acc[j][i] = 0.f;

    for (int j = 0; j <= l; j++) {
        const float* Wj = conv_w + (size_t)(off + j) * 1024 * 512;
        const float* Xj = &g_xbuf[j][b][0][0];
        for (int kk0 = 0; kk0 < 512; kk0 += 16) {
            __syncthreads();
            {   // A: 128 rows (o) x 16 cols (kk)
                int cg = tid & 3;
                int row = tid >> 2;
#pragma unroll
                for (int p = 0; p < 2; p++) {
                    int r_ = row + p * 64;
                    float4 v = *(const float4*)(Wj + (size_t)(o0 + r_) * 512 + kk0 + cg * 4);
                    As[cg * 4 + 0][r_] = v.x; As[cg * 4 + 1][r_] = v.y;
                    As[cg * 4 + 2][r_] = v.z; As[cg * 4 + 3][r_] = v.w;
                }
            }
            {   // B: Bs[kk][wl] = Xj[(kkg>>1)*XW + w0 + wl + (kkg&1)]
                int row = tid >> 4;          // 0..15
                int colb = (tid & 15) * 8;
                int kkg = kk0 + row;
                const float* src = Xj + (size_t)(kkg >> 1) * XW + w0 + (kkg & 1) + colb;
#pragma unroll
                for (int q = 0; q < 8; q++) Bs[row][colb + q] = src[q];
            }
            __syncthreads();
#pragma unroll
            for (int k = 0; k < 16; k++) {
                float4 a0 = *(const float4*)&As[k][ty * 8];
                float4 a1 = *(const float4*)&As[k][ty * 8 + 4];
                float4 b0 = *(const float4*)&Bs[k][tx * 8];
                float4 b1 = *(const float4*)&Bs[k][tx * 8 + 4];
                float av[8] = {a0.x, a0.y, a0.z, a0.w, a1.x, a1.y, a1.z, a1.w};
                float bv[8] = {b0.x, b0.y, b0.z, b0.w, b1.x, b1.y, b1.z, b1.w};
#pragma unroll
                for (int jw = 0; jw < 8; jw++)
#pragma unroll
                    for (int io = 0; io < 8; io++) acc[jw][io] = fmaf(av[io], bv[jw], acc[jw][io]);
            }
        }
    }
    // epilogue: + summed biases, store to g_ig[b][w][o]
    float bias[8];
#pragma unroll
    for (int i = 0; i < 8; i++) {
        int o = o0 + ty * 8 + i;
        float s = 0.f;
        for (int j = 0; j <= l; j++) s += conv_b[(off + j) * 1024 + o];
        bias[i] = s;
    }
#pragma unroll
    for (int jw = 0; jw < 8; jw++) {
        float* dst = &g_ig[b][w0 + tx * 8 + jw][o0 + ty * 8];
        float4 v0 = make_float4(acc[jw][0] + bias[0], acc[jw][1] + bias[1],
                                acc[jw][2] + bias[2], acc[jw][3] + bias[3]);
        float4 v1 = make_float4(acc[jw][4] + bias[4], acc[jw][5] + bias[5],
                                acc[jw][6] + bias[6], acc[jw][7] + bias[7]);
        *(float4*)dst = v0;
        *(float4*)(dst + 4) = v1;
    }
}

// ------------------------- LSTM scan (4-CTA cluster per batch) -------------
// CTA rank r owns gate rows [r*256, r*256+256) of rec_w[l] (bf16 in smem).
// Per step: matvec -> cluster sync -> redundant LSTM update via DSMEM -> sync.
__global__ void __launch_bounds__(256, 1) __cluster_dims__(4, 1, 1)
scan_kernel(int l,
            const float* __restrict__ hidden, const float* __restrict__ context,
            const float* __restrict__ rec_w, const float* __restrict__ rec_b,
            const float* __restrict__ attn_w, float* __restrict__ out) {
    extern __shared__ uint8_t sm8[];
    uint32_t* rw_s = (uint32_t*)sm8;                 // [128][256] bf16x2
    float* gbuf = (float*)(sm8 + 131072);            // 256
    float* hx_s = gbuf + 256;                        // 256
    float* cx_s = hx_s + 256;                        // 256
    float* red  = cx_s + 256;                        // 8

    const int t = threadIdx.x;
    const int b = blockIdx.x >> 2;
    uint32_t rank;
    asm("mov.u32 %0, %%cluster_ctarank;" : "=r"(rank));
    const int nl = l + 1;
    const int G = (int)rank * 256 + t;

    // load rec_w slice as bf16 pairs: rw_s[hh][g] = pack(rw[G'][2hh], rw[G'][2hh+1])
    const float* rwl = rec_w + (size_t)l * 1024 * 256;
    for (int idx = t; idx < 128 * 256; idx += 256) {
        int g = idx & 255, hh = idx >> 8;
        const float* p = rwl + (size_t)(rank * 256 + g) * 256 + hh * 2;
        __nv_bfloat162 pk = __floats2bfloat162_rn(p[0], p[1]);
        rw_s[hh * 256 + g] = *(uint32_t*)&pk;
    }
    // init carries (identical in all 4 CTAs)
    hx_s[t] = hidden[((size_t)((nl * 32 + b) * 256 + t)) * 2 + 1];
    cx_s[t] = context[((size_t)((l * 32 + b) * 256 + t)) * 2 + 1];

    const float rb_t = rec_b[l * 1024 + G];
    const float aw_t = attn_w[l * 256 + t];

    const uint32_t la = smem_u32(gbuf) + t * 4;
    const uint32_t adr0 = mapa_rank(la, 0), adr1 = mapa_rank(la, 1);
    const uint32_t adr2 = mapa_rank(la, 2), adr3 = mapa_rank(la, 3);

    const float* igb = &g_ig[b][0][0];
    float* gx_next = &g_xbuf[nl][b][0][0];
    const int lane = t & 31, warp = t >> 5;

    cluster_sync_();   // weights + carries ready everywhere

    for (int w = 0; w < 512; w++) {
        // ---- matvec: gate pre-activation for row G ----
        float igv = igb[(size_t)w * 1024 + G];
        float acc = rb_t;
        const float2* hx2 = (const float2*)hx_s;
#pragma unroll 8
        for (int hh = 0; hh < 128; hh++) {
            uint32_t u = rw_s[hh * 256 + t];
            float2 h2 = hx2[hh];
            acc = fmaf(__uint_as_float(u << 16), h2.x, acc);
            acc = fmaf(__uint_as_float(u & 0xffff0000u), h2.y, acc);
        }
        gbuf[t] = acc + igv;
        cluster_sync_();   // all gate quarters published

        // ---- LSTM update (redundant, bitwise identical in all 4 CTAs) ----
        float gi = ld_cluster_f32(adr0);
        float gf = ld_cluster_f32(adr1);
        float gc = ld_cluster_f32(adr2);
        float go = ld_cluster_f32(adr3);
        float cx = sigm(gf) * cx_s[t] + sigm(gi) * tanhf(gc);
        float hr = sigm(go) * tanhf(cx);
        cx_s[t] = cx;

        // attention: a = sigmoid(sum_h hr[h]*aw[h])
        float p = hr * aw_t;
#pragma unroll
        for (int o_ = 16; o_ > 0; o_ >>= 1) p += __shfl_xor_sync(0xffffffffu, p, o_);
        if (lane == 0) red[warp] = p;
        __syncthreads();
        float s = 0.f;
#pragma unroll
        for (int q = 0; q < 8; q++) s += red[q];
        float a = sigm(s);

        float hx = (w < 511) ? hr * a : hr;
        hx_s[t] = hx;

        if (rank == 0) {
            gx_next[(size_t)t * XW + 1 + w] = hx;   // next layer's conv input
            if (w >= 510) {
                int tt = w - 510;
                out[((size_t)((nl * 32 + b) * 256 + t)) * 2 + tt] = hx;
                out[NC_OFF + ((size_t)((l * 32 + b) * 256 + t)) * 2 + tt] = cx;
            }
            if (w < 511 && t == 0)
                out[ATTN_OFF + (size_t)(l * 32 + b) * 511 + w] = a;
        }
        cluster_sync_();   // hx stable; peers done reading gbuf
    }
}

// ---------------------------------------------------------------------------
extern "C" void kernel_launch(void* const* d_in, const int* in_sizes, int n_in,
                              void* d_out, int out_size) {
    const float* input   = (const float*)d_in[0];
    const float* hidden  = (const float*)d_in[1];
    const float* context = (const float*)d_in[2];
    const float* emb_w   = (const float*)d_in[3];
    const float* emb_b   = (const float*)d_in[4];
    const float* conv_w  = (const float*)d_in[5];
    const float* conv_b  = (const float*)d_in[6];
    const float* rec_w   = (const float*)d_in[7];
    const float* rec_b   = (const float*)d_in[8];
    const float* attn_w  = (const float*)d_in[9];
    float* out = (float*)d_out;

    cudaFuncSetAttribute(scan_kernel, cudaFuncAttributeMaxDynamicSharedMemorySize, SCAN_SMEM);

    init_pads_kernel<<<128, 256>>>(hidden);
    emb_gemm_kernel<<<dim3(2, 4, 32), 256>>>(input, emb_w, emb_b);
    copy_x0_kernel<<<64, 256>>>(out);

    for (int l = 0; l < 3; l++) {
        conv_gemm_kernel<<<dim3(8, 4, 32), 256>>>(l, conv_w, conv_b);
        scan_kernel<<<128, 256, SCAN_SMEM>>>(l, hidden, context, rec_w, rec_b, attn_w, out);
    }
}

// round 9
// speedup vs baseline: 1.1177x; 1.1177x over previous
#include <cuda_runtime.h>
#include <cuda_bf16.h>
#include <cstdint>

// ---------------------------------------------------------------------------
// Problem: B=32, NINP=128, NHID=256, W=512, K=2, NLAYERS=3
//
// Scratch:
//   g_xbuf[lv][b][c][p], p in [0,513): p=0 is left pad = hidden[lv][b][c][1],
//                        p=1+w is x_list[lv][b][c][w]. Row stride XW=520.
//   g_ig[b][w][o]: conv-bank gate pre-activations for the current layer.
//
// Output (float32): [0,65536) x[:,:,:,-2:] (4,32,256,2)
//                   [65536,114688) nc[:,:,:,-2:] (3,32,256,2)
//                   [114688,163744) attns (3,32,511)
// ---------------------------------------------------------------------------

#define XW 520
#define NC_OFF   65536
#define ATTN_OFF 114688

// scan smem layout (bytes)
#define RW_OFF  0         // 131072: [32][256] uint4 (bf16x2 x4)
#define GB_OFF  131072    // 8192:   gb[2][4][256] float
#define HX_OFF  139264    // 1024:   hx[256]
#define RED_OFF 140288    // 32:     red[8]
#define MB_OFF  140320    // 16:     mbar[2] (u64)
#define SCAN_SMEM 140352

__device__ float g_xbuf[4][32][256][XW];   // ~68 MB
__device__ float g_ig[32][512][1024];      // ~67 MB

__device__ __forceinline__ float tanh_ap(float x) {
    float y; asm("tanh.approx.f32 %0, %1;" : "=f"(y) : "f"(x)); return y;
}
__device__ __forceinline__ float sigm_ap(float x) {
    return 0.5f * tanh_ap(0.5f * x) + 0.5f;
}

__device__ __forceinline__ uint32_t smem_u32(const void* p) {
    return (uint32_t)__cvta_generic_to_shared(p);
}
__device__ __forceinline__ uint32_t mapa_rank(uint32_t a, uint32_t r) {
    uint32_t d;
    asm("mapa.shared::cluster.u32 %0, %1, %2;" : "=r"(d) : "r"(a), "r"(r));
    return d;
}
__device__ __forceinline__ void st_cluster_f32(uint32_t a, float v) {
    asm volatile("st.shared::cluster.f32 [%0], %1;" :: "r"(a), "f"(v) : "memory");
}
__device__ __forceinline__ void mbar_init(uint32_t a, uint32_t cnt) {
    asm volatile("mbarrier.init.shared.b64 [%0], %1;" :: "r"(a), "r"(cnt) : "memory");
}
__device__ __forceinline__ void mbar_arrive_cluster(uint32_t a) {
    asm volatile("mbarrier.arrive.release.cluster.shared::cluster.b64 _, [%0];"
                 :: "r"(a) : "memory");
}
__device__ __forceinline__ void mbar_wait_acq(uint32_t a, uint32_t par) {
    uint32_t done;
    asm volatile(
        "{\n\t.reg .pred p;\n\t"
        "mbarrier.try_wait.parity.acquire.cluster.shared::cta.b64 p, [%1], %2;\n\t"
        "selp.b32 %0, 1, 0, p;\n\t}"
        : "=r"(done) : "r"(a), "r"(par) : "memory");
    if (!done) {
        asm volatile(
            "{\n\t.reg .pred P1;\n\t"
            "WL_%=:\n\t"
            "mbarrier.try_wait.parity.acquire.cluster.shared::cta.b64 P1, [%0], %1, 0x989680;\n\t"
            "@P1 bra.uni WD_%=;\n\t"
            "bra.uni WL_%=;\n\t"
            "WD_%=:\n\t}"
            :: "r"(a), "r"(par) : "memory");
    }
}
__device__ __forceinline__ void cluster_sync_() {
    asm volatile("barrier.cluster.arrive.aligned;" ::: "memory");
    asm volatile("barrier.cluster.wait.aligned;" ::: "memory");
}

// ------------------------- pad init ----------------------------------------
__global__ void init_pads_kernel(const float* __restrict__ hidden) {
    int idx = blockIdx.x * blockDim.x + threadIdx.x;   // 4*32*256 = 32768
    if (idx >= 4 * 32 * 256) return;
    int lv = idx >> 13;
    int b  = (idx >> 8) & 31;
    int c  = idx & 255;
    g_xbuf[lv][b][c][0] = hidden[((size_t)((lv * 32 + b) * 256 + c)) * 2 + 1];
}

// ------------------------- x0 tail copy to output --------------------------
__global__ void copy_x0_kernel(float* __restrict__ out) {
    int idx = blockIdx.x * blockDim.x + threadIdx.x;   // 16384
    if (idx >= 16384) return;
    int tt = idx & 1;
    int h  = (idx >> 1) & 255;
    int b  = idx >> 9;
    out[idx] = g_xbuf[0][b][h][511 + tt];
}

// ------------------------- embedding GEMM ----------------------------------
// g_xbuf[0][b][o][1+w] = emb_b[o] + sum_c emb_w[o][c] * input[b][c][w]
__global__ void __launch_bounds__(256, 2)
emb_gemm_kernel(const float* __restrict__ input,
                const float* __restrict__ emb_w,
                const float* __restrict__ emb_b) {
    __shared__ float As[16][132];
    __shared__ float Bs[16][136];
    const int o0 = blockIdx.x * 128, w0 = blockIdx.y * 128, b = blockIdx.z;
    const int tid = threadIdx.x, tx = tid & 15, ty = tid >> 4;

    float acc[8][8];
#pragma unroll
    for (int j = 0; j < 8; j++)
#pragma unroll
        for (int i = 0; i < 8; i++) acc[j][i] = 0.f;

    for (int k0 = 0; k0 < 128; k0 += 16) {
        __syncthreads();
        {   // A: 128 rows (o) x 16 cols (k)
            int cg = tid & 3;
            int row = tid >> 2;
#pragma unroll
            for (int p = 0; p < 2; p++) {
                int r_ = row + p * 64;
                float4 v = *(const float4*)(emb_w + (size_t)(o0 + r_) * 128 + k0 + cg * 4);
                As[cg * 4 + 0][r_] = v.x; As[cg * 4 + 1][r_] = v.y;
                As[cg * 4 + 2][r_] = v.z; As[cg * 4 + 3][r_] = v.w;
            }
        }
        {   // B: 16 rows (k) x 128 cols (w)
            for (int i = tid; i < 512; i += 256) {
                int r = i >> 5, q = i & 31;
                float4 v = *(const float4*)(input + (size_t)(b * 128 + k0 + r) * 512 + w0 + q * 4);
                Bs[r][q * 4 + 0] = v.x; Bs[r][q * 4 + 1] = v.y;
                Bs[r][q * 4 + 2] = v.z; Bs[r][q * 4 + 3] = v.w;
            }
        }
        __syncthreads();
#pragma unroll
        for (int k = 0; k < 16; k++) {
            float4 a0 = *(const float4*)&As[k][ty * 8];
            float4 a1 = *(const float4*)&As[k][ty * 8 + 4];
            float4 b0 = *(const float4*)&Bs[k][tx * 4];
            float4 b1 = *(const float4*)&Bs[k][64 + tx * 4];
            float av[8] = {a0.x, a0.y, a0.z, a0.w, a1.x, a1.y, a1.z, a1.w};
            float bv[8] = {b0.x, b0.y, b0.z, b0.w, b1.x, b1.y, b1.z, b1.w};
#pragma unroll
            for (int j = 0; j < 8; j++)
#pragma unroll
                for (int i = 0; i < 8; i++) acc[j][i] = fmaf(av[i], bv[j], acc[j][i]);
        }
    }
#pragma unroll
    for (int i = 0; i < 8; i++) {
        int o = o0 + ty * 8 + i;
        float bias = emb_b[o];
        float* dst = &g_xbuf[0][b][o][1 + w0];
#pragma unroll
        for (int j = 0; j < 4; j++) dst[tx * 4 + j] = acc[j][i] + bias;
#pragma unroll
        for (int j = 0; j < 4; j++) dst[64 + tx * 4 + j] = acc[4 + j][i] + bias;
    }
}

// ------------------------- conv-bank GEMM ----------------------------------
// g_ig[b][w][o] = sum_{j<=l} ( conv_b[off+j][o]
//               + sum_{kk<512} conv_w[off+j][o][kk] * g_xbuf[j][b][kk>>1][w + (kk&1)] )
__global__ void __launch_bounds__(256, 2)
conv_gemm_kernel(int l, const float* __restrict__ conv_w, const float* __restrict__ conv_b) {
    __shared__ float As[16][132];
    __shared__ float Bs[16][136];
    const int o0 = blockIdx.x * 128, w0 = blockIdx.y * 128, b = blockIdx.z;
    const int off = (l * (l + 1)) >> 1;
    const int tid = threadIdx.x, tx = tid & 15, ty = tid >> 4;

    float acc[8][8];
#pragma unroll
    for (int j = 0; j < 8; j++)
#pragma unroll
        for (int i = 0; i < 8; i++) acc[j][i] = 0.f;

    for (int j = 0; j <= l; j++) {
        const float* Wj = conv_w + (size_t)(off + j) * 1024 * 512;
        const float* Xj = &g_xbuf[j][b][0][0];
        for (int kk0 = 0; kk0 < 512; kk0 += 16) {
            __syncthreads();
            {   // A: 128 rows (o) x 16 cols (kk)
                int cg = tid & 3;
                int row = tid >> 2;
#pragma unroll
                for (int p = 0; p < 2; p++) {
                    int r_ = row + p * 64;
                    float4 v = *(const float4*)(Wj + (size_t)(o0 + r_) * 512 + kk0 + cg * 4);
                    As[cg * 4 + 0][r_] = v.x; As[cg * 4 + 1][r_] = v.y;
                    As[cg * 4 + 2][r_] = v.z; As[cg * 4 + 3][r_] = v.w;
                }
            }
            {   // B: Bs[kk][wl] = Xj[(kkg>>1)*XW + w0 + wl + (kkg&1)]
                int row = tid >> 4;
                int colb = (tid & 15) * 8;
                int kkg = kk0 + row;
                const float* src = Xj + (size_t)(kkg >> 1) * XW + w0 + (kkg & 1) + colb;
#pragma unroll
                for (int q = 0; q < 8; q++) Bs[row][colb + q] = src[q];
            }
            __syncthreads();
#pragma unroll
            for (int k = 0; k < 16; k++) {
                float4 a0 = *(const float4*)&As[k][ty * 8];
                float4 a1 = *(const float4*)&As[k][ty * 8 + 4];
                float4 b0 = *(const float4*)&Bs[k][tx * 4];
                float4 b1 = *(const float4*)&Bs[k][64 + tx * 4];
                float av[8] = {a0.x, a0.y, a0.z, a0.w, a1.x, a1.y, a1.z, a1.w};
                float bv[8] = {b0.x, b0.y, b0.z, b0.w, b1.x, b1.y, b1.z, b1.w};
#pragma unroll
                for (int jw = 0; jw < 8; jw++)
#pragma unroll
                    for (int io = 0; io < 8; io++) acc[jw][io] = fmaf(av[io], bv[jw], acc[jw][io]);
            }
        }
    }
    float bias[8];
#pragma unroll
    for (int i = 0; i < 8; i++) {
        int o = o0 + ty * 8 + i;
        float s = 0.f;
        for (int j = 0; j <= l; j++) s += conv_b[(off + j) * 1024 + o];
        bias[i] = s;
    }
#pragma unroll
    for (int jw = 0; jw < 8; jw++) {
        int wl = (jw < 4) ? (tx * 4 + jw) : (64 + tx * 4 + (jw - 4));
        float* dst = &g_ig[b][w0 + wl][o0 + ty * 8];
        float4 v0 = make_float4(acc[jw][0] + bias[0], acc[jw][1] + bias[1],
                                acc[jw][2] + bias[2], acc[jw][3] + bias[3]);
        float4 v1 = make_float4(acc[jw][4] + bias[4], acc[jw][5] + bias[5],
                                acc[jw][6] + bias[6], acc[jw][7] + bias[7]);
        *(float4*)dst = v0;
        *(float4*)(dst + 4) = v1;
    }
}

// ------------------------- LSTM scan (4-CTA cluster per batch) -------------
// CTA rank r owns gate rows [r*256, r*256+256) of rec_w[l] (bf16x2 in smem,
// vector-packed for LDS.128). Push-model gate exchange: each CTA stores its
// quarter into all 4 CTAs' double-buffered slots and arrives (release) on
// every CTA's mbarrier; each CTA waits (acquire) on ONE local mbarrier per
// step. LSTM update + attention are recomputed redundantly (bitwise identical)
// in all 4 CTAs, so hx/cx never cross CTAs.
__global__ void __launch_bounds__(256, 1) __cluster_dims__(4, 1, 1)
scan_kernel(int l,
            const float* __restrict__ hidden, const float* __restrict__ context,
            const float* __restrict__ rec_w, const float* __restrict__ rec_b,
            const float* __restrict__ attn_w, float* __restrict__ out) {
    extern __shared__ uint8_t sm8[];
    uint4*  rw4  = (uint4*)(sm8 + RW_OFF);       // [32][256]
    float*  gbL  = (float*)(sm8 + GB_OFF);       // [2][4][256]
    float*  hx_s = (float*)(sm8 + HX_OFF);       // [256]
    float*  red  = (float*)(sm8 + RED_OFF);      // [8]

    const int t = threadIdx.x;
    const int b = blockIdx.x >> 2;
    uint32_t rank;
    asm("mov.u32 %0, %%cluster_ctarank;" : "=r"(rank));
    const int nl = l + 1;
    const int G = (int)rank * 256 + t;

    // pack rec_w row G into vector smem: rw4[q][t] covers h = 8q..8q+7
    const float* rwl = rec_w + (size_t)l * 1024 * 256;
#pragma unroll 4
    for (int q = 0; q < 32; q++) {
        const float* p = rwl + (size_t)G * 256 + q * 8;
        __nv_bfloat162 p0 = __floats2bfloat162_rn(p[0], p[1]);
        __nv_bfloat162 p1 = __floats2bfloat162_rn(p[2], p[3]);
        __nv_bfloat162 p2 = __floats2bfloat162_rn(p[4], p[5]);
        __nv_bfloat162 p3 = __floats2bfloat162_rn(p[6], p[7]);
        uint4 u;
        u.x = *(uint32_t*)&p0; u.y = *(uint32_t*)&p1;
        u.z = *(uint32_t*)&p2; u.w = *(uint32_t*)&p3;
        rw4[(q << 8) + t] = u;
    }
    hx_s[t] = hidden[((size_t)((nl * 32 + b) * 256 + t)) * 2 + 1];
    float cx = context[((size_t)((l * 32 + b) * 256 + t)) * 2 + 1];

    const float rb_t = rec_b[l * 1024 + G];
    const float aw_t = attn_w[l * 256 + t];

    const uint32_t gb_base = smem_u32(sm8 + GB_OFF);
    const uint32_t mb_base = smem_u32(sm8 + MB_OFF);
    uint32_t gb_peer[4], mb_peer[4];
#pragma unroll
    for (int r = 0; r < 4; r++) {
        gb_peer[r] = mapa_rank(gb_base, r);
        mb_peer[r] = mapa_rank(mb_base, r);
    }
    if (t == 0) { mbar_init(mb_base, 1024); mbar_init(mb_base + 8, 1024); }
    __syncthreads();
    cluster_sync_();   // barriers + weights + hx ready cluster-wide

    const float* igb = &g_ig[b][0][0];
    float* gx_next = &g_xbuf[nl][b][0][0];
    const int lane = t & 31, warp = t >> 5;
    const uint32_t my_slot = (uint32_t)(((rank << 8) + t) << 2);  // within gb[buf]

    for (int w = 0; w < 512; w++) {
        const int buf = w & 1;
        float igv = igb[(size_t)w * 1024 + G];   // issued early, hidden by matvec

        // ---- matvec: gate pre-activation for row G ----
        float a0 = 0.f, a1 = 0.f, a2 = 0.f, a3 = 0.f;
        const float4* hxf4 = (const float4*)hx_s;
#pragma unroll
        for (int q = 0; q < 32; q++) {
            uint4 u = rw4[(q << 8) + t];
            float4 ha = hxf4[2 * q];
            float4 hb = hxf4[2 * q + 1];
            a0 = fmaf(__uint_as_float(u.x << 16), ha.x, a0);
            a1 = fmaf(__uint_as_float(u.x),       ha.y, a1);
            a2 = fmaf(__uint_as_float(u.y << 16), ha.z, a2);
            a3 = fmaf(__uint_as_float(u.y),       ha.w, a3);
            a0 = fmaf(__uint_as_float(u.z << 16), hb.x, a0);
            a1 = fmaf(__uint_as_float(u.z),       hb.y, a1);
            a2 = fmaf(__uint_as_float(u.w << 16), hb.z, a2);
            a3 = fmaf(__uint_as_float(u.w),       hb.w, a3);
        }
        float gate = ((a0 + a1) + (a2 + a3)) + rb_t + igv;

        // ---- push my gate value to all 4 CTAs, then arrive (release) ----
        uint32_t so = (uint32_t)(buf << 12) + my_slot;   // buf*4096 bytes
#pragma unroll
        for (int r = 0; r < 4; r++) st_cluster_f32(gb_peer[r] + so, gate);
#pragma unroll
        for (int r = 0; r < 4; r++) mbar_arrive_cluster(mb_peer[r] + (buf << 3));

        // ---- wait for all 1024 gate values (local barrier, acquire) ----
        mbar_wait_acq(mb_base + (buf << 3), (uint32_t)((w >> 1) & 1));

        // ---- LSTM update (redundant, bitwise identical in all CTAs) ----
        const float* gq = gbL + buf * 1024;
        float gi = gq[t], gf = gq[256 + t], gc = gq[512 + t], go = gq[768 + t];
        cx = sigm_ap(gf) * cx + sigm_ap(gi) * tanh_ap(gc);
        float hr = sigm_ap(go) * tanh_ap(cx);

        // attention: a = sigmoid(sum_h hr[h]*aw[h])
        float p = hr * aw_t;
#pragma unroll
        for (int o_ = 16; o_ > 0; o_ >>= 1) p += __shfl_xor_sync(0xffffffffu, p, o_);
        if (lane == 0) red[warp] = p;
        __syncthreads();
        float s = 0.f;
#pragma unroll
        for (int q = 0; q < 8; q++) s += red[q];
        float a = sigm_ap(s);

        float hx = (w < 511) ? hr * a : hr;
        hx_s[t] = hx;

        if (rank == 0) {
            gx_next[(size_t)t * XW + 1 + w] = hx;   // next layer's conv input
            if (w >= 510) {
                int tt = w - 510;
                out[((size_t)((nl * 32 + b) * 256 + t)) * 2 + tt] = hx;
                out[NC_OFF + ((size_t)((l * 32 + b) * 256 + t)) * 2 + tt] = cx;
            }
            if (w < 511 && t == 0)
                out[ATTN_OFF + (size_t)(l * 32 + b) * 511 + w] = a;
        }
        __syncthreads();   // hx_s stable before next matvec; red reusable
    }
    cluster_sync_();   // don't exit while peers may still write our smem
}

// ---------------------------------------------------------------------------
extern "C" void kernel_launch(void* const* d_in, const int* in_sizes, int n_in,
                              void* d_out, int out_size) {
    const float* input   = (const float*)d_in[0];
    const float* hidden  = (const float*)d_in[1];
    const float* context = (const float*)d_in[2];
    const float* emb_w   = (const float*)d_in[3];
    const float* emb_b   = (const float*)d_in[4];
    const float* conv_w  = (const float*)d_in[5];
    const float* conv_b  = (const float*)d_in[6];
    const float* rec_w   = (const float*)d_in[7];
    const float* rec_b   = (const float*)d_in[8];
    const float* attn_w  = (const float*)d_in[9];
    float* out = (float*)d_out;

    cudaFuncSetAttribute(scan_kernel, cudaFuncAttributeMaxDynamicSharedMemorySize, SCAN_SMEM);

    init_pads_kernel<<<128, 256>>>(hidden);
    emb_gemm_kernel<<<dim3(2, 4, 32), 256>>>(input, emb_w, emb_b);
    copy_x0_kernel<<<64, 256>>>(out);

    for (int l = 0; l < 3; l++) {
        conv_gemm_kernel<<<dim3(8, 4, 32), 256>>>(l, conv_w, conv_b);
        scan_kernel<<<128, 256, SCAN_SMEM>>>(l, hidden, context, rec_w, rec_b, attn_w, out);
    }
}

// round 10
// speedup vs baseline: 1.1254x; 1.0069x over previous
#include <cuda_runtime.h>
#include <cuda_bf16.h>
#include <cstdint>

// ---------------------------------------------------------------------------
// Problem: B=32, NINP=128, NHID=256, W=512, K=2, NLAYERS=3
//
// Scratch:
//   g_xbuf[lv][b][c][p], p in [0,513): p=0 is left pad = hidden[lv][b][c][1],
//                        p=1+w is x_list[lv][b][c][w]. Row stride XW=520.
//   g_ig[b][w][o]: conv-bank gate pre-activations for the current layer.
//   g_wT[jb][kk][o]: conv_w transposed (kk-major) for cp.async tile loads.
//
// Output (float32): [0,65536) x[:,:,:,-2:] (4,32,256,2)
//                   [65536,114688) nc[:,:,:,-2:] (3,32,256,2)
//                   [114688,163744) attns (3,32,511)
// ---------------------------------------------------------------------------

#define XW 520
#define NC_OFF   65536
#define ATTN_OFF 114688

// scan smem layout (bytes)
#define RW_OFF  0         // 131072: [32][256] uint4 (bf16x2 x4)
#define HR_OFF  131072    // 2048:   hr[2][256] float
#define GQ_OFF  133120    // 1024:   gq[256] float
#define RED_OFF 134144    // 32:     red[8]
#define MB_OFF  134176    // 16:     mbar[2]
#define SCAN_SMEM 134208

__device__ float g_xbuf[4][32][256][XW];   // ~68 MB
__device__ float g_ig[32][512][1024];      // ~67 MB
__device__ float g_wT[6][512][1024];       // ~12.6 MB

__device__ __forceinline__ float tanh_ap(float x) {
    float y; asm("tanh.approx.f32 %0, %1;" : "=f"(y) : "f"(x)); return y;
}
__device__ __forceinline__ float sigm_ap(float x) {
    return 0.5f * tanh_ap(0.5f * x) + 0.5f;
}
__device__ __forceinline__ uint32_t smem_u32(const void* p) {
    return (uint32_t)__cvta_generic_to_shared(p);
}
__device__ __forceinline__ uint32_t mapa_rank(uint32_t a, uint32_t r) {
    uint32_t d;
    asm("mapa.shared::cluster.u32 %0, %1, %2;" : "=r"(d) : "r"(a), "r"(r));
    return d;
}
__device__ __forceinline__ void st_cluster_f32(uint32_t a, float v) {
    asm volatile("st.shared::cluster.f32 [%0], %1;" :: "r"(a), "f"(v) : "memory");
}
__device__ __forceinline__ void mbar_init(uint32_t a, uint32_t cnt) {
    asm volatile("mbarrier.init.shared.b64 [%0], %1;" :: "r"(a), "r"(cnt) : "memory");
}
__device__ __forceinline__ void mbar_arrive_cluster(uint32_t a) {
    asm volatile("mbarrier.arrive.release.cluster.shared::cluster.b64 _, [%0];"
                 :: "r"(a) : "memory");
}
__device__ __forceinline__ void mbar_wait_acq(uint32_t a, uint32_t par) {
    uint32_t done;
    asm volatile(
        "{\n\t.reg .pred p;\n\t"
        "mbarrier.try_wait.parity.acquire.cluster.shared::cta.b64 p, [%1], %2;\n\t"
        "selp.b32 %0, 1, 0, p;\n\t}"
        : "=r"(done) : "r"(a), "r"(par) : "memory");
    if (!done) {
        asm volatile(
            "{\n\t.reg .pred P1;\n\t"
            "WL_%=:\n\t"
            "mbarrier.try_wait.parity.acquire.cluster.shared::cta.b64 P1, [%0], %1, 0x989680;\n\t"
            "@P1 bra.uni WD_%=;\n\t"
            "bra.uni WL_%=;\n\t"
            "WD_%=:\n\t}"
            :: "r"(a), "r"(par) : "memory");
    }
}
__device__ __forceinline__ void cluster_sync_() {
    asm volatile("barrier.cluster.arrive.aligned;" ::: "memory");
    asm volatile("barrier.cluster.wait.aligned;" ::: "memory");
}
__device__ __forceinline__ void cp16(void* dst, const void* src) {
    asm volatile("cp.async.cg.shared.global [%0], [%1], 16;"
                 :: "r"(smem_u32(dst)), "l"(src) : "memory");
}
__device__ __forceinline__ void cp4(void* dst, const void* src) {
    asm volatile("cp.async.ca.shared.global [%0], [%1], 4;"
                 :: "r"(smem_u32(dst)), "l"(src) : "memory");
}
__device__ __forceinline__ void cp_commit() {
    asm volatile("cp.async.commit_group;" ::: "memory");
}

// ------------------------- conv_w transpose --------------------------------
__global__ void transpose_w_kernel(const float* __restrict__ conv_w) {
    __shared__ float tile[32][33];
    int jb = blockIdx.z, o0 = blockIdx.y * 32, k0 = blockIdx.x * 32;
    int tx = threadIdx.x, ty = threadIdx.y;   // (32, 8)
#pragma unroll
    for (int i = 0; i < 32; i += 8)
        tile[ty + i][tx] = conv_w[((size_t)jb * 1024 + o0 + ty + i) * 512 + k0 + tx];
    __syncthreads();
#pragma unroll
    for (int i = 0; i < 32; i += 8)
        g_wT[jb][k0 + ty + i][o0 + tx] = tile[tx][ty + i];
}

// ------------------------- pad init ----------------------------------------
__global__ void init_pads_kernel(const float* __restrict__ hidden) {
    int idx = blockIdx.x * blockDim.x + threadIdx.x;   // 32768
    if (idx >= 4 * 32 * 256) return;
    int lv = idx >> 13;
    int b  = (idx >> 8) & 31;
    int c  = idx & 255;
    g_xbuf[lv][b][c][0] = hidden[((size_t)((lv * 32 + b) * 256 + c)) * 2 + 1];
}

// ------------------------- x0 tail copy to output --------------------------
__global__ void copy_x0_kernel(float* __restrict__ out) {
    int idx = blockIdx.x * blockDim.x + threadIdx.x;   // 16384
    if (idx >= 16384) return;
    int tt = idx & 1;
    int h  = (idx >> 1) & 255;
    int b  = idx >> 9;
    out[idx] = g_xbuf[0][b][h][511 + tt];
}

// ------------------------- embedding GEMM ----------------------------------
__global__ void __launch_bounds__(256, 2)
emb_gemm_kernel(const float* __restrict__ input,
                const float* __restrict__ emb_w,
                const float* __restrict__ emb_b) {
    __shared__ float As[16][132];
    __shared__ float Bs[16][136];
    const int o0 = blockIdx.x * 128, w0 = blockIdx.y * 128, b = blockIdx.z;
    const int tid = threadIdx.x, tx = tid & 15, ty = tid >> 4;

    float acc[8][8];
#pragma unroll
    for (int j = 0; j < 8; j++)
#pragma unroll
        for (int i = 0; i < 8; i++) acc[j][i] = 0.f;

    for (int k0 = 0; k0 < 128; k0 += 16) {
        __syncthreads();
        {
            int cg = tid & 3;
            int row = tid >> 2;
#pragma unroll
            for (int p = 0; p < 2; p++) {
                int r_ = row + p * 64;
                float4 v = *(const float4*)(emb_w + (size_t)(o0 + r_) * 128 + k0 + cg * 4);
                As[cg * 4 + 0][r_] = v.x; As[cg * 4 + 1][r_] = v.y;
                As[cg * 4 + 2][r_] = v.z; As[cg * 4 + 3][r_] = v.w;
            }
        }
        {
            for (int i = tid; i < 512; i += 256) {
                int r = i >> 5, q = i & 31;
                float4 v = *(const float4*)(input + (size_t)(b * 128 + k0 + r) * 512 + w0 + q * 4);
                Bs[r][q * 4 + 0] = v.x; Bs[r][q * 4 + 1] = v.y;
                Bs[r][q * 4 + 2] = v.z; Bs[r][q * 4 + 3] = v.w;
            }
        }
        __syncthreads();
#pragma unroll
        for (int k = 0; k < 16; k++) {
            float4 a0 = *(const float4*)&As[k][ty * 8];
            float4 a1 = *(const float4*)&As[k][ty * 8 + 4];
            float4 b0 = *(const float4*)&Bs[k][tx * 4];
            float4 b1 = *(const float4*)&Bs[k][64 + tx * 4];
            float av[8] = {a0.x, a0.y, a0.z, a0.w, a1.x, a1.y, a1.z, a1.w};
            float bv[8] = {b0.x, b0.y, b0.z, b0.w, b1.x, b1.y, b1.z, b1.w};
#pragma unroll
            for (int j = 0; j < 8; j++)
#pragma unroll
                for (int i = 0; i < 8; i++) acc[j][i] = fmaf(av[i], bv[j], acc[j][i]);
        }
    }
#pragma unroll
    for (int i = 0; i < 8; i++) {
        int o = o0 + ty * 8 + i;
        float bias = emb_b[o];
        float* dst = &g_xbuf[0][b][o][1 + w0];
#pragma unroll
        for (int j = 0; j < 4; j++) dst[tx * 4 + j] = acc[j][i] + bias;
#pragma unroll
        for (int j = 0; j < 4; j++) dst[64 + tx * 4 + j] = acc[4 + j][i] + bias;
    }
}

// ------------------------- conv-bank GEMM (cp.async double-buffered) -------
__global__ void __launch_bounds__(256, 2)
conv_gemm_kernel(int l, const float* __restrict__ conv_b) {
    __shared__ float As[2][16][132];
    __shared__ float Bs[2][16][136];
    const int o0 = blockIdx.x * 128, w0 = blockIdx.y * 128, b = blockIdx.z;
    const int off = (l * (l + 1)) >> 1;
    const int tid = threadIdx.x, tx = tid & 15, ty = tid >> 4;
    const int total = 32 * (l + 1);

    float acc[8][8];
#pragma unroll
    for (int j = 0; j < 8; j++)
#pragma unroll
        for (int i = 0; i < 8; i++) acc[j][i] = 0.f;

    auto load_tile = [&](int buf, int kt) {
        int jl = kt >> 5;
        int kk0 = (kt & 31) << 4;
        const float* WT = &g_wT[off + jl][kk0][0];
        // A: 16 rows x 128 floats from g_wT (contiguous)
#pragma unroll
        for (int s = 0; s < 2; s++) {
            int idx = tid + s * 256;
            int row = idx >> 5, c4 = idx & 31;
            cp16(&As[buf][row][c4 * 4], WT + (size_t)row * 1024 + o0 + c4 * 4);
        }
        // B: 16 rows x 128 floats with per-row (kk&1) shift
        {
            int row = tid >> 4;
            int colb = (tid & 15) * 8;
            int kkg = kk0 + row;
            const float* src = &g_xbuf[jl][b][kkg >> 1][w0 + (kkg & 1) + colb];
            if ((kkg & 1) == 0) {
                cp16(&Bs[buf][row][colb], src);
                cp16(&Bs[buf][row][colb + 4], src + 4);
            } else {
#pragma unroll
                for (int q = 0; q < 8; q++) cp4(&Bs[buf][row][colb + q], src + q);
            }
        }
    };

    load_tile(0, 0); cp_commit();
    if (total > 1) { load_tile(1, 1); cp_commit(); }

    for (int kt = 0; kt < total; kt++) {
        if (kt + 1 < total) asm volatile("cp.async.wait_group 1;" ::: "memory");
        else                asm volatile("cp.async.wait_group 0;" ::: "memory");
        __syncthreads();
        int buf = kt & 1;
#pragma unroll
        for (int k = 0; k < 16; k++) {
            float4 a0 = *(const float4*)&As[buf][k][ty * 8];
            float4 a1 = *(const float4*)&As[buf][k][ty * 8 + 4];
            float4 b0 = *(const float4*)&Bs[buf][k][tx * 4];
            float4 b1 = *(const float4*)&Bs[buf][k][64 + tx * 4];
            float av[8] = {a0.x, a0.y, a0.z, a0.w, a1.x, a1.y, a1.z, a1.w};
            float bv[8] = {b0.x, b0.y, b0.z, b0.w, b1.x, b1.y, b1.z, b1.w};
#pragma unroll
            for (int jw = 0; jw < 8; jw++)
#pragma unroll
                for (int io = 0; io < 8; io++) acc[jw][io] = fmaf(av[io], bv[jw], acc[jw][io]);
        }
        __syncthreads();
        if (kt + 2 < total) { load_tile(buf, kt + 2); cp_commit(); }
    }

    float bias[8];
#pragma unroll
    for (int i = 0; i < 8; i++) {
        int o = o0 + ty * 8 + i;
        float s = 0.f;
        for (int j = 0; j <= l; j++) s += conv_b[(off + j) * 1024 + o];
        bias[i] = s;
    }
#pragma unroll
    for (int jw = 0; jw < 8; jw++) {
        int wl = (jw < 4) ? (tx * 4 + jw) : (64 + tx * 4 + (jw - 4));
        float* dst = &g_ig[b][w0 + wl][o0 + ty * 8];
        float4 v0 = make_float4(acc[jw][0] + bias[0], acc[jw][1] + bias[1],
                                acc[jw][2] + bias[2], acc[jw][3] + bias[3]);
        float4 v1 = make_float4(acc[jw][4] + bias[4], acc[jw][5] + bias[5],
                                acc[jw][6] + bias[6], acc[jw][7] + bias[7]);
        *(float4*)dst = v0;
        *(float4*)(dst + 4) = v1;
    }
}

// ------------------------- LSTM scan (4-CTA cluster per batch) -------------
// CTA rank r owns h in [64r, 64r+64): weight rows {g*256 + 64r + hl}. The
// LSTM update is LOCAL; only the 64 hr values cross CTAs (double-buffered,
// one mbarrier per step, 256 arrivals). The scalar attention gate a is folded
// into the next step's matvec: gate = a_prev * dot(rw, hr_prev) + rb + ig.
__global__ void __launch_bounds__(256, 1) __cluster_dims__(4, 1, 1)
scan_kernel(int l,
            const float* __restrict__ hidden, const float* __restrict__ context,
            const float* __restrict__ rec_w, const float* __restrict__ rec_b,
            const float* __restrict__ attn_w, float* __restrict__ out) {
    extern __shared__ uint8_t sm8[];
    uint4* rw4   = (uint4*)(sm8 + RW_OFF);     // [32][256]
    float* hrbuf = (float*)(sm8 + HR_OFF);     // [2][256]
    float* gq    = (float*)(sm8 + GQ_OFF);     // [256]
    float* red   = (float*)(sm8 + RED_OFF);    // [8]

    const int t = threadIdx.x;
    const int b = blockIdx.x >> 2;
    uint32_t rank;
    asm("mov.u32 %0, %%cluster_ctarank;" : "=r"(rank));
    const int nl = l + 1;
    const int g_idx = t >> 6, hl = t & 63;
    const int G = g_idx * 256 + 64 * (int)rank + hl;   // my gate row

    // pack weight row G: rw4[q][t] = bf16x2 x4 of rw[G][8q..8q+7]
    const float* rwl = rec_w + (size_t)l * 1024 * 256;
#pragma unroll 4
    for (int q = 0; q < 32; q++) {
        const float* p = rwl + (size_t)G * 256 + q * 8;
        __nv_bfloat162 p0 = __floats2bfloat162_rn(p[0], p[1]);
        __nv_bfloat162 p1 = __floats2bfloat162_rn(p[2], p[3]);
        __nv_bfloat162 p2 = __floats2bfloat162_rn(p[4], p[5]);
        __nv_bfloat162 p3 = __floats2bfloat162_rn(p[6], p[7]);
        uint4 u;
        u.x = *(uint32_t*)&p0; u.y = *(uint32_t*)&p1;
        u.z = *(uint32_t*)&p2; u.w = *(uint32_t*)&p3;
        rw4[(q << 8) + t] = u;
    }
    // prefill buf1 with initial hx (raw; a_prev=1 at step 0)
    hrbuf[256 + t] = hidden[((size_t)((nl * 32 + b) * 256 + t)) * 2 + 1];

    const int h_glob = 64 * (int)rank + hl;            // for update threads (t<64, hl==t)
    float cx = context[((size_t)((l * 32 + b) * 256 + h_glob)) * 2 + 1];
    float hr_prev = 0.f;

    const float rb_t = rec_b[l * 1024 + G];
    const float aw_t = attn_w[l * 256 + t];

    const uint32_t hr_base = smem_u32(sm8 + HR_OFF);
    const uint32_t mb_base = smem_u32(sm8 + MB_OFF);
    uint32_t hr_peer[4], mb_peer[4];
#pragma unroll
    for (int r = 0; r < 4; r++) {
        hr_peer[r] = mapa_rank(hr_base, r);
        mb_peer[r] = mapa_rank(mb_base, r);
    }
    if (t == 0) { mbar_init(mb_base, 256); mbar_init(mb_base + 8, 256); }
    __syncthreads();
    cluster_sync_();

    const float* igb = &g_ig[b][0][0];
    float* gx_next = &g_xbuf[nl][b][0][0];
    const int lane = t & 31, warp = t >> 5;

    for (int w = 0; w < 512; w++) {
        const int jprev = (w + 1) & 1;        // buffer holding hr^{w-1}
        if (w > 0) mbar_wait_acq(mb_base + (uint32_t)(jprev << 3),
                                 (uint32_t)(((w - 1) >> 1) & 1));

        const float* hrp = hrbuf + (jprev << 8);

        // a_prev = sigmoid(sum_h hr_prev[h]*aw[h]) (redundant in all CTAs)
        float p = hrp[t] * aw_t;
#pragma unroll
        for (int o_ = 16; o_ > 0; o_ >>= 1) p += __shfl_xor_sync(0xffffffffu, p, o_);
        if (lane == 0) red[warp] = p;
        __syncthreads();
        float s = 0.f;
#pragma unroll
        for (int q = 0; q < 8; q++) s += red[q];
        float a_prev = (w > 0) ? sigm_ap(s) : 1.f;

        float igv = igb[(size_t)w * 1024 + G];

        // matvec over hr_prev
        float a0 = 0.f, a1 = 0.f, a2 = 0.f, a3 = 0.f;
        const float4* hx4 = (const float4*)hrp;
#pragma unroll
        for (int q = 0; q < 32; q++) {
            uint4 u = rw4[(q << 8) + t];
            float4 ha = hx4[2 * q];
            float4 hb = hx4[2 * q + 1];
            a0 = fmaf(__uint_as_float(u.x << 16), ha.x, a0);
            a1 = fmaf(__uint_as_float(u.x),       ha.y, a1);
            a2 = fmaf(__uint_as_float(u.y << 16), ha.z, a2);
            a3 = fmaf(__uint_as_float(u.y),       ha.w, a3);
            a0 = fmaf(__uint_as_float(u.z << 16), hb.x, a0);
            a1 = fmaf(__uint_as_float(u.z),       hb.y, a1);
            a2 = fmaf(__uint_as_float(u.w << 16), hb.z, a2);
            a3 = fmaf(__uint_as_float(u.w),       hb.w, a3);
        }
        gq[t] = a_prev * (((a0 + a1) + (a2 + a3))) + rb_t + igv;
        __syncthreads();

        if (t < 64) {
            // previous-step outputs (hx^{w-1} = hr_prev * a_prev)
            if (w > 0) {
                float hxprev = hr_prev * a_prev;
                gx_next[(size_t)h_glob * XW + w] = hxprev;   // col 1+(w-1)
                if (w == 511)
                    out[((size_t)((nl * 32 + b) * 256 + h_glob)) * 2 + 0] = hxprev;
            }
            float gi = gq[t], gf = gq[64 + t], gc = gq[128 + t], go = gq[192 + t];
            cx = sigm_ap(gf) * cx + sigm_ap(gi) * tanh_ap(gc);
            float hr = sigm_ap(go) * tanh_ap(cx);
            if (w >= 510)
                out[NC_OFF + ((size_t)((l * 32 + b) * 256 + h_glob)) * 2 + (w - 510)] = cx;
            if (w == 511) {
                out[((size_t)((nl * 32 + b) * 256 + h_glob)) * 2 + 1] = hr;  // ungated
                gx_next[(size_t)h_glob * XW + 512] = hr;
            } else {
                uint32_t soff = (uint32_t)((((w & 1) << 8) + h_glob) << 2);
#pragma unroll
                for (int r = 0; r < 4; r++) st_cluster_f32(hr_peer[r] + soff, hr);
#pragma unroll
                for (int r = 0; r < 4; r++)
                    mbar_arrive_cluster(mb_peer[r] + (uint32_t)((w & 1) << 3));
            }
            hr_prev = hr;
        }
        if (rank == 0 && t == 0 && w > 0)
            out[ATTN_OFF + (size_t)(l * 32 + b) * 511 + (w - 1)] = a_prev;
    }
    cluster_sync_();   // keep smem alive for in-flight peer stores
}

// ---------------------------------------------------------------------------
extern "C" void kernel_launch(void* const* d_in, const int* in_sizes, int n_in,
                              void* d_out, int out_size) {
    const float* input   = (const float*)d_in[0];
    const float* hidden  = (const float*)d_in[1];
    const float* context = (const float*)d_in[2];
    const float* emb_w   = (const float*)d_in[3];
    const float* emb_b   = (const float*)d_in[4];
    const float* conv_w  = (const float*)d_in[5];
    const float* conv_b  = (const float*)d_in[6];
    const float* rec_w   = (const float*)d_in[7];
    const float* rec_b   = (const float*)d_in[8];
    const float* attn_w  = (const float*)d_in[9];
    float* out = (float*)d_out;

    cudaFuncSetAttribute(scan_kernel, cudaFuncAttributeMaxDynamicSharedMemorySize, SCAN_SMEM);

    transpose_w_kernel<<<dim3(16, 32, 6), dim3(32, 8)>>>(conv_w);
    init_pads_kernel<<<128, 256>>>(hidden);
    emb_gemm_kernel<<<dim3(2, 4, 32), 256>>>(input, emb_w, emb_b);
    copy_x0_kernel<<<64, 256>>>(out);

    for (int l = 0; l < 3; l++) {
        conv_gemm_kernel<<<dim3(8, 4, 32), 256>>>(l, conv_b);
        scan_kernel<<<128, 256, SCAN_SMEM>>>(l, hidden, context, rec_w, rec_b, attn_w, out);
    }
}